// round 3
// baseline (speedup 1.0000x reference)
#include <cuda_runtime.h>
#include <cstdint>

#define NSYM  12
#define BATCH 16384
#define HID   100
#define GATES 400

// scratch: per-row (a, symbol) after 11 expansion steps
__device__ float2 d_syma[BATCH];

// ---------------------------------------------------------------------------
// JAX threefry2x32 (20 rounds), bit-exact
// ---------------------------------------------------------------------------
__device__ __forceinline__ uint32_t rotl32(uint32_t x, int r) {
    return (x << r) | (x >> (32 - r));
}

__device__ __forceinline__ void threefry2x32(uint32_t k0, uint32_t k1,
                                             uint32_t x0, uint32_t x1,
                                             uint32_t& o0, uint32_t& o1)
{
    uint32_t k2 = k0 ^ k1 ^ 0x1BD11BDAu;
    x0 += k0; x1 += k1;
#define RG(a,b,c,d) \
    x0 += x1; x1 = rotl32(x1,a); x1 ^= x0; \
    x0 += x1; x1 = rotl32(x1,b); x1 ^= x0; \
    x0 += x1; x1 = rotl32(x1,c); x1 ^= x0; \
    x0 += x1; x1 = rotl32(x1,d); x1 ^= x0;
    RG(13,15,26,6)   x0 += k1; x1 += k2 + 1u;
    RG(17,29,16,24)  x0 += k2; x1 += k0 + 2u;
    RG(13,15,26,6)   x0 += k0; x1 += k1 + 3u;
    RG(17,29,16,24)  x0 += k1; x1 += k2 + 4u;
    RG(13,15,26,6)   x0 += k2; x1 += k0 + 5u;
#undef RG
    o0 = x0; o1 = x1;
}

// ---------------------------------------------------------------------------
// Kernel A: grammar expansion. One thread per batch row.
// PARTITIONABLE threefry (modern JAX default, jax_threefry_partitionable=True):
//   split(key(42), 11):  keys[t] = threefry((0,42), x0=0, x1=t) -> (o0, o1)
//   uniform bits, elem L of flat (B,N): threefry(key_t, x0=0, x1=L), bits=o0^o1
// gumbel = -log(-log(u)); argmax first-max tie rule;
// straight-through scale a = (1 - softmax_max) + softmax_max.
// ---------------------------------------------------------------------------
__global__ void expand_kernel(const float* __restrict__ one_hot,
                              const float* __restrict__ grammar)
{
    __shared__ uint32_t kb[22];           // interleaved: key_t = (kb[2t], kb[2t+1])
    __shared__ float gm[NSYM * NSYM];
    int t = threadIdx.x;
    if (t < 11) {
        uint32_t o0, o1;
        threefry2x32(0u, 42u, 0u, (uint32_t)t, o0, o1);   // foldlike split
        kb[2 * t] = o0; kb[2 * t + 1] = o1;
    }
    if (t < NSYM * NSYM) gm[t] = grammar[t];
    __syncthreads();

    int b = blockIdx.x * blockDim.x + t;
    if (b >= BATCH) return;

    int s = 0;
#pragma unroll
    for (int n = 0; n < NSYM; ++n)
        if (one_hot[b * NSYM + n] > 0.5f) s = n;

    float a = 1.0f;
    for (int step = 0; step < 11; ++step) {
        if (s == NSYM - 1) break;   // terminal symbol: row frozen forever
        uint32_t key0 = kb[2 * step], key1 = kb[2 * step + 1];
        float z[NSYM];
        float zmax = -1e30f;
        int m = 0;
#pragma unroll
        for (int n = 0; n < NSYM; ++n) {
            uint32_t L = (uint32_t)(b * NSYM + n);      // 64-bit counter, hi=0
            uint32_t o0, o1;
            threefry2x32(key0, key1, 0u, L, o0, o1);
            uint32_t bits = o0 ^ o1;                    // 32-bit fold
            float f = __uint_as_float(0x3F800000u | (bits >> 9)) - 1.0f;
            float u = (f == 0.0f) ? 1e-20f : f;
            float gu = -logf(-logf(u));
            float zz = __fadd_rn(__fmul_rn(a, gm[s * NSYM + n]), gu);
            z[n] = zz;
            if (zz > zmax) { zmax = zz; m = n; }
        }
        // straight-through value at the argmax: (1 - s_m) + s_m
        float den = 0.0f;
#pragma unroll
        for (int n = 0; n < NSYM; ++n) den += expf(z[n] - zmax);
        float sm = 1.0f / den;
        a = (1.0f - sm) + sm;
        s = m;
    }
    d_syma[b] = make_float2(a, __int_as_float(s));
}

// ---------------------------------------------------------------------------
// Kernel B: the single LSTM chain (lane t=11), 16384 strictly-sequential steps
// on one SM. 200 compute threads, 2 gate outputs each via fma.rn.f32x2,
// W_hh entirely in registers (100 x b64 per thread), h broadcast via smem.
// ---------------------------------------------------------------------------
__device__ __forceinline__ unsigned long long ffma2(unsigned long long a,
                                                    unsigned long long b,
                                                    unsigned long long c)
{
    unsigned long long d;
    asm("fma.rn.f32x2 %0, %1, %2, %3;" : "=l"(d) : "l"(a), "l"(b), "l"(c));
    return d;
}
__device__ __forceinline__ float lo32(unsigned long long v) { return __uint_as_float((uint32_t)v); }
__device__ __forceinline__ float hi32(unsigned long long v) { return __uint_as_float((uint32_t)(v >> 32)); }
__device__ __forceinline__ unsigned long long pack2(float x, float y) {
    return (unsigned long long)__float_as_uint(x) |
           ((unsigned long long)__float_as_uint(y) << 32);
}
// full-precision activations (keep until green; speed pass later)
__device__ __forceinline__ float sigmoid_p(float x) {
    return 1.0f / (1.0f + expf(-x));
}

__global__ void __launch_bounds__(224, 1)
lstm_kernel(const float* __restrict__ Wih,
            const float* __restrict__ Whh,
            float* __restrict__ out)
{
    __shared__ __align__(16) unsigned long long h2[HID];   // {h[j], h[j]} packed
    __shared__ __align__(8)  float acts[GATES];            // activated gates
    __shared__ float2 wih2[NSYM * 200];                    // [sym][pair]

    int tid = threadIdx.x;

    // stage W_ih columns as pairs: wih2[s*200+p] = {Wih[2p][s], Wih[2p+1][s]}
    for (int idx = tid; idx < NSYM * 200; idx += 224) {
        int sidx = idx / 200, p = idx % 200;
        wih2[idx] = make_float2(Wih[(2 * p) * NSYM + sidx],
                                Wih[(2 * p + 1) * NSYM + sidx]);
    }
    if (tid < HID) h2[tid] = 0ull;

    // W_hh rows 2*tid and 2*tid+1 into registers, packed per-j
    unsigned long long w[HID];
    if (tid < 200) {
        const float* r = Whh + (2 * tid) * HID;
#pragma unroll
        for (int j = 0; j < HID; ++j) w[j] = pack2(r[j], r[j + HID]);
    }
    float ck = 0.0f;                       // c[tid] for tid < 100
    __syncthreads();

    float2 sa = d_syma[0];
    const bool isg = (tid >= 100 && tid < 150);   // g-gate pairs -> tanh

    for (int b = 0; b < BATCH; ++b) {
        float2 sa_next = d_syma[(b + 1) & (BATCH - 1)];   // prefetch (L1-hit)

        if (tid < 200) {
            int s = __float_as_int(sa.y);
            float2 wi = wih2[s * 200 + tid];
            unsigned long long a0 = 0, a1 = 0, a2 = 0, a3 = 0;
            const ulonglong2* hv = (const ulonglong2*)h2;
#pragma unroll
            for (int jj = 0; jj < 50; jj += 2) {
                ulonglong2 e0 = hv[jj];
                a0 = ffma2(w[2 * jj],     e0.x, a0);
                a1 = ffma2(w[2 * jj + 1], e0.y, a1);
                ulonglong2 e1 = hv[jj + 1];
                a2 = ffma2(w[2 * jj + 2], e1.x, a2);
                a3 = ffma2(w[2 * jj + 3], e1.y, a3);
            }
            float x0 = (lo32(a0) + lo32(a1)) + (lo32(a2) + lo32(a3));
            float x1 = (hi32(a0) + hi32(a1)) + (hi32(a2) + hi32(a3));
            x0 += sa.x * wi.x;
            x1 += sa.x * wi.y;
            float y0, y1;
            if (isg) { y0 = tanhf(x0);     y1 = tanhf(x1);     }
            else     { y0 = sigmoid_p(x0); y1 = sigmoid_p(x1); }
            ((float2*)acts)[tid] = make_float2(y0, y1);
        }
        __syncthreads();

        if (tid < HID) {
            float i_ = acts[tid];
            float f_ = acts[HID + tid];
            float g_ = acts[2 * HID + tid];
            float o_ = acts[3 * HID + tid];
            ck = f_ * ck + i_ * g_;
            float h = o_ * tanhf(ck);
            out[b * HID + tid] = h;          // fire-and-forget STG
            h2[tid] = pack2(h, h);
        }
        __syncthreads();
        sa = sa_next;
    }
}

// ---------------------------------------------------------------------------
// Inputs identified by element count (robust to harness input ordering):
//   one_hot     : 16384*12 = 196608
//   grammar_mat : 12*12    = 144
//   W_ih        : 400*12   = 4800
//   W_hh        : 400*100  = 40000
// ---------------------------------------------------------------------------
extern "C" void kernel_launch(void* const* d_in, const int* in_sizes, int n_in,
                              void* d_out, int out_size)
{
    const float* one_hot = nullptr;
    const float* grammar = nullptr;
    const float* Wih     = nullptr;
    const float* Whh     = nullptr;
    for (int i = 0; i < n_in; ++i) {
        switch (in_sizes[i]) {
            case 196608: one_hot = (const float*)d_in[i]; break;
            case 144:    grammar = (const float*)d_in[i]; break;
            case 4800:   Wih     = (const float*)d_in[i]; break;
            case 40000:  Whh     = (const float*)d_in[i]; break;
            default: break;
        }
    }
    float* out = (float*)d_out;                     // [16384, 100]

    expand_kernel<<<BATCH / 256, 256>>>(one_hot, grammar);
    lstm_kernel<<<1, 224>>>(Wih, Whh, out);
}